// round 1
// baseline (speedup 1.0000x reference)
#include <cuda_runtime.h>

#define BB 16
#define C1 512
#define C2 1024
#define CTOT 1536
#define HH 64
#define HH2 32
#define HW 4096
#define HW2 1024
#define OUTC 256
#define PP 2048
#define NPIX 65536   // BB * HW

// ---- scratch (static device globals; no allocation allowed) ----
__device__ float g_sample[(size_t)BB * CTOT * HW];   // concat(pool(p1), resize(pool(p2))) [b][c][hw]
__device__ float g_emb[(size_t)NPIX * OUTC];         // embeddings [pixel][out]
__device__ float g_en[NPIX];                         // ||e||^2 per pixel
__device__ float g_cn[PP];                           // ||c||^2 per centroid

// ============================================================
// Kernel 1: 3x3 avg pool (zero pad, /9) on p1, write channels [0,512)
// One block per (b, c) plane of 64x64.
// ============================================================
__global__ void pool1_kernel(const float* __restrict__ p1) {
    __shared__ float s[HW];
    int plane = blockIdx.x;                    // b*C1 + c
    const float* in = p1 + (size_t)plane * HW;
    int b = plane / C1, c = plane - b * C1;
    float* out = g_sample + ((size_t)b * CTOT + c) * HW;
    for (int i = threadIdx.x; i < HW; i += blockDim.x) s[i] = in[i];
    __syncthreads();
    for (int i = threadIdx.x; i < HW; i += blockDim.x) {
        int y = i >> 6, x = i & 63;
        float sum = 0.f;
        #pragma unroll
        for (int dy = -1; dy <= 1; ++dy) {
            int yy = y + dy;
            if ((unsigned)yy < 64u) {
                const float* r = s + yy * 64;
                #pragma unroll
                for (int dx = -1; dx <= 1; ++dx) {
                    int xx = x + dx;
                    if ((unsigned)xx < 64u) sum += r[xx];
                }
            }
        }
        out[i] = sum * (1.f / 9.f);
    }
}

// jax bilinear upsample 32->64 taps: src = 0.5*i - 0.25, clamp indices.
__device__ __forceinline__ void lin_taps(int i, int& j0, int& j1, float& w1) {
    float xf = 0.5f * (float)i - 0.25f;
    float fl = floorf(xf);
    int j = (int)fl;
    w1 = xf - fl;               // weight of j+1
    j0 = j < 0 ? 0 : j;
    j1 = (j + 1 > 31) ? 31 : (j + 1);
}

// ============================================================
// Kernel 2: 3x3 avg pool on p2 plane (32x32) then bilinear 32->64,
// write channels [512, 1536). One block per (b, c2).
// ============================================================
__global__ void pool2_resize_kernel(const float* __restrict__ p2) {
    __shared__ float s[HW2];
    __shared__ float q[HW2];
    int plane = blockIdx.x;                    // b*C2 + c
    const float* in = p2 + (size_t)plane * HW2;
    int b = plane / C2, c = plane - b * C2;
    float* out = g_sample + ((size_t)b * CTOT + C1 + c) * HW;
    for (int i = threadIdx.x; i < HW2; i += blockDim.x) s[i] = in[i];
    __syncthreads();
    for (int i = threadIdx.x; i < HW2; i += blockDim.x) {
        int y = i >> 5, x = i & 31;
        float sum = 0.f;
        #pragma unroll
        for (int dy = -1; dy <= 1; ++dy) {
            int yy = y + dy;
            if ((unsigned)yy < 32u) {
                const float* r = s + yy * 32;
                #pragma unroll
                for (int dx = -1; dx <= 1; ++dx) {
                    int xx = x + dx;
                    if ((unsigned)xx < 32u) sum += r[xx];
                }
            }
        }
        q[i] = sum * (1.f / 9.f);
    }
    __syncthreads();
    for (int i = threadIdx.x; i < HW; i += blockDim.x) {
        int y = i >> 6, x = i & 63;
        int y0, y1, x0, x1; float wy, wx;
        lin_taps(y, y0, y1, wy);
        lin_taps(x, x0, x1, wx);
        float v0 = q[y0 * 32 + x0] * (1.f - wx) + q[y0 * 32 + x1] * wx;
        float v1 = q[y1 * 32 + x0] * (1.f - wx) + q[y1 * 32 + x1] * wx;
        out[i] = v0 * (1.f - wy) + v1 * wy;
    }
}

// ============================================================
// Kernel 3: projection GEMM.
// emb[m, o] = sum_c sample[b(m)][c][hw(m)] * W[o][c] + bias[o]
// M = 65536, N = 256, K = 1536. Tiles 128x128, 8x8 micro-tile, K-step 8.
// A is M-contiguous (column-major), B is K-contiguous.
// ============================================================
__global__ void __launch_bounds__(256) proj_gemm_kernel(
    const float* __restrict__ W, const float* __restrict__ bias) {
    __shared__ float As[8][128];
    __shared__ float Bs[8][128];
    int t = threadIdx.x;
    int tx = t & 15, ty = t >> 4;
    int m0 = blockIdx.x * 128;
    int n0 = blockIdx.y * 128;
    int b = m0 >> 12;          // 128 | 4096 so whole tile is one batch
    int hw0 = m0 & 4095;

    int ak = t >> 5;           // 0..7   (k row in A tile)
    int am = (t & 31) << 2;    // 0..124 (m, float4)
    int bn = t >> 1;           // 0..127 (n row of W)
    int bk = (t & 1) << 2;     // 0 or 4 (k, float4)

    const float* Aptr = g_sample + ((size_t)b * CTOT + ak) * HW + hw0 + am;
    const float* Bptr = W + (size_t)(n0 + bn) * CTOT + bk;

    float acc[8][8];
    #pragma unroll
    for (int i = 0; i < 8; ++i)
        #pragma unroll
        for (int j = 0; j < 8; ++j) acc[i][j] = 0.f;

    for (int k0 = 0; k0 < CTOT; k0 += 8) {
        float4 av = *(const float4*)(Aptr + (size_t)k0 * HW);
        float4 bv = *(const float4*)(Bptr + k0);
        __syncthreads();
        *(float4*)&As[ak][am] = av;
        Bs[bk + 0][bn] = bv.x;
        Bs[bk + 1][bn] = bv.y;
        Bs[bk + 2][bn] = bv.z;
        Bs[bk + 3][bn] = bv.w;
        __syncthreads();
        #pragma unroll
        for (int kk = 0; kk < 8; ++kk) {
            float4 a0 = *(const float4*)&As[kk][ty * 8];
            float4 a1 = *(const float4*)&As[kk][ty * 8 + 4];
            float4 b0 = *(const float4*)&Bs[kk][tx * 8];
            float4 b1 = *(const float4*)&Bs[kk][tx * 8 + 4];
            float a[8] = {a0.x, a0.y, a0.z, a0.w, a1.x, a1.y, a1.z, a1.w};
            float bb[8] = {b0.x, b0.y, b0.z, b0.w, b1.x, b1.y, b1.z, b1.w};
            #pragma unroll
            for (int i = 0; i < 8; ++i)
                #pragma unroll
                for (int j = 0; j < 8; ++j)
                    acc[i][j] = fmaf(a[i], bb[j], acc[i][j]);
        }
    }

    float bs[8];
    #pragma unroll
    for (int j = 0; j < 8; ++j) bs[j] = bias[n0 + tx * 8 + j];

    #pragma unroll
    for (int i = 0; i < 8; ++i) {
        int m = m0 + ty * 8 + i;
        float* dst = g_emb + (size_t)m * OUTC + n0 + tx * 8;
        float4 o0, o1;
        o0.x = acc[i][0] + bs[0]; o0.y = acc[i][1] + bs[1];
        o0.z = acc[i][2] + bs[2]; o0.w = acc[i][3] + bs[3];
        o1.x = acc[i][4] + bs[4]; o1.y = acc[i][5] + bs[5];
        o1.z = acc[i][6] + bs[6]; o1.w = acc[i][7] + bs[7];
        *(float4*)dst = o0;
        *(float4*)(dst + 4) = o1;
    }
}

// ============================================================
// Kernel 4: squared norms. One warp per row:
// rows [0, NPIX) -> g_emb rows, rows [NPIX, NPIX+P) -> centroid rows.
// ============================================================
__global__ void norms_kernel(const float* __restrict__ cents) {
    int warp = (blockIdx.x * blockDim.x + threadIdx.x) >> 5;
    int lane = threadIdx.x & 31;
    const float* row;
    float* dst;
    if (warp < NPIX) {
        row = g_emb + (size_t)warp * OUTC;
        dst = g_en + warp;
    } else if (warp < NPIX + PP) {
        row = cents + (size_t)(warp - NPIX) * OUTC;
        dst = g_cn + (warp - NPIX);
    } else {
        return;
    }
    float s = 0.f;
    for (int k = lane; k < OUTC; k += 32) {
        float v = row[k];
        s = fmaf(v, v, s);
    }
    #pragma unroll
    for (int off = 16; off; off >>= 1) s += __shfl_xor_sync(0xffffffffu, s, off);
    if (lane == 0) *dst = s;
}

// ============================================================
// Kernel 5: distance GEMM + fused top-3 + softmin score.
// Block: 128 pixels x all 2048 centroids (16 chunks of 128).
// Thread owns 8 pixels x 8 centroid-cols per chunk and keeps a running
// per-pixel top-3 of (||c||^2 - 2 e.c) (||e||^2 added at the end; sqrt
// is monotone so selection on dist^2 is exact).
// ============================================================
__global__ void __launch_bounds__(256) dist_kernel(
    const float* __restrict__ cents, float* __restrict__ out) {
    __shared__ float smem[6144];               // 24 KB: A/B tiles, later top-3 merge
    float (*As)[128] = (float(*)[128])smem;            // [8][128]
    float (*Bs)[128] = (float(*)[128])(smem + 1024);   // [8][128]

    int t = threadIdx.x;
    int tx = t & 15, ty = t >> 4;
    int m0 = blockIdx.x * 128;
    int r = t >> 1;            // 0..127
    int kg = (t & 1) << 2;     // 0 or 4

    const float* Aptr = g_emb + (size_t)(m0 + r) * OUTC + kg;

    float top0[8], top1[8], top2[8];
    #pragma unroll
    for (int i = 0; i < 8; ++i) { top0[i] = 3.4e38f; top1[i] = 3.4e38f; top2[i] = 3.4e38f; }

    for (int ch = 0; ch < 16; ++ch) {
        int n0 = ch * 128;
        const float* Bptr = cents + (size_t)(n0 + r) * OUTC + kg;

        float acc[8][8];
        #pragma unroll
        for (int i = 0; i < 8; ++i)
            #pragma unroll
            for (int j = 0; j < 8; ++j) acc[i][j] = 0.f;

        for (int k0 = 0; k0 < OUTC; k0 += 8) {
            float4 av = *(const float4*)(Aptr + k0);
            float4 bv = *(const float4*)(Bptr + k0);
            __syncthreads();
            As[kg + 0][r] = av.x; As[kg + 1][r] = av.y;
            As[kg + 2][r] = av.z; As[kg + 3][r] = av.w;
            Bs[kg + 0][r] = bv.x; Bs[kg + 1][r] = bv.y;
            Bs[kg + 2][r] = bv.z; Bs[kg + 3][r] = bv.w;
            __syncthreads();
            #pragma unroll
            for (int kk = 0; kk < 8; ++kk) {
                float4 a0 = *(const float4*)&As[kk][ty * 8];
                float4 a1 = *(const float4*)&As[kk][ty * 8 + 4];
                float4 b0 = *(const float4*)&Bs[kk][tx * 8];
                float4 b1 = *(const float4*)&Bs[kk][tx * 8 + 4];
                float a[8] = {a0.x, a0.y, a0.z, a0.w, a1.x, a1.y, a1.z, a1.w};
                float bb[8] = {b0.x, b0.y, b0.z, b0.w, b1.x, b1.y, b1.z, b1.w};
                #pragma unroll
                for (int i = 0; i < 8; ++i)
                    #pragma unroll
                    for (int j = 0; j < 8; ++j)
                        acc[i][j] = fmaf(a[i], bb[j], acc[i][j]);
            }
        }

        #pragma unroll
        for (int j = 0; j < 8; ++j) {
            float cn = g_cn[n0 + tx * 8 + j];
            #pragma unroll
            for (int i = 0; i < 8; ++i) {
                float v = cn - 2.f * acc[i][j];
                if (v < top2[i]) {
                    if (v < top1[i]) {
                        top2[i] = top1[i];
                        if (v < top0[i]) { top1[i] = top0[i]; top0[i] = v; }
                        else             { top1[i] = v; }
                    } else {
                        top2[i] = v;
                    }
                }
            }
        }
    }

    __syncthreads();   // done with As/Bs; reuse smem for the merge
    #pragma unroll
    for (int i = 0; i < 8; ++i) {
        int pix = ty * 8 + i;
        float* dst = smem + pix * 48 + tx * 3;
        dst[0] = top0[i]; dst[1] = top1[i]; dst[2] = top2[i];
    }
    __syncthreads();

    if (t < 128) {
        float t0 = 3.4e38f, t1 = 3.4e38f, t2 = 3.4e38f;
        const float* src = smem + t * 48;
        #pragma unroll
        for (int q = 0; q < 48; ++q) {
            float v = src[q];
            if (v < t2) {
                if (v < t1) {
                    t2 = t1;
                    if (v < t0) { t1 = t0; t0 = v; }
                    else        { t1 = v; }
                } else {
                    t2 = v;
                }
            }
        }
        float en = g_en[m0 + t];
        float d0 = sqrtf(en + t0);
        float d1 = sqrtf(en + t1);
        float d2 = sqrtf(en + t2);
        float w0 = 1.f / (1.f + expf(d0 - d1) + expf(d0 - d2));
        out[m0 + t] = w0 * d0;
    }
}

// ============================================================
// Launcher
// ============================================================
extern "C" void kernel_launch(void* const* d_in, const int* in_sizes, int n_in,
                              void* d_out, int out_size) {
    const float* p1 = (const float*)d_in[0];
    const float* p2 = (const float*)d_in[1];
    const float* pw = (const float*)d_in[2];
    const float* pb = (const float*)d_in[3];
    const float* ce = (const float*)d_in[4];
    float* out = (float*)d_out;
    (void)in_sizes; (void)n_in; (void)out_size;   // K is fixed at 3

    pool1_kernel<<<BB * C1, 256>>>(p1);
    pool2_resize_kernel<<<BB * C2, 256>>>(p2);
    proj_gemm_kernel<<<dim3(512, 2), 256>>>(pw, pb);
    norms_kernel<<<(NPIX + PP) * 32 / 256, 256>>>(ce);
    dist_kernel<<<512, 256>>>(ce, out);
}

// round 2
// speedup vs baseline: 1.0039x; 1.0039x over previous
#include <cuda_runtime.h>

#define BB 16
#define C1 512
#define C2 1024
#define CTOT 1536
#define HH 64
#define HH2 32
#define HW 4096
#define HW2 1024
#define OUTC 256
#define PP 2048
#define NPIX 65536   // BB * HW

// ---- scratch (static device globals; no allocation allowed) ----
__device__ float g_sample[(size_t)BB * CTOT * HW];   // concat(pool(p1), resize(pool(p2))) [b][c][hw]
__device__ float g_emb[(size_t)NPIX * OUTC];         // embeddings [pixel][out]
__device__ float g_en[NPIX];                         // ||e||^2 per pixel
__device__ float g_cn[PP];                           // ||c||^2 per centroid

// ============================================================
// Kernel 1: 3x3 avg pool (zero pad, /9) on p1, write channels [0,512)
// One block per (b, c) plane of 64x64.
// ============================================================
__global__ void pool1_kernel(const float* __restrict__ p1) {
    __shared__ float s[HW];
    int plane = blockIdx.x;                    // b*C1 + c
    const float* in = p1 + (size_t)plane * HW;
    int b = plane / C1, c = plane - b * C1;
    float* out = g_sample + ((size_t)b * CTOT + c) * HW;
    for (int i = threadIdx.x; i < HW; i += blockDim.x) s[i] = in[i];
    __syncthreads();
    for (int i = threadIdx.x; i < HW; i += blockDim.x) {
        int y = i >> 6, x = i & 63;
        float sum = 0.f;
        #pragma unroll
        for (int dy = -1; dy <= 1; ++dy) {
            int yy = y + dy;
            if ((unsigned)yy < 64u) {
                const float* r = s + yy * 64;
                #pragma unroll
                for (int dx = -1; dx <= 1; ++dx) {
                    int xx = x + dx;
                    if ((unsigned)xx < 64u) sum += r[xx];
                }
            }
        }
        out[i] = sum * (1.f / 9.f);
    }
}

// jax bilinear upsample 32->64 taps: src = 0.5*i - 0.25, clamp indices.
__device__ __forceinline__ void lin_taps(int i, int& j0, int& j1, float& w1) {
    float xf = 0.5f * (float)i - 0.25f;
    float fl = floorf(xf);
    int j = (int)fl;
    w1 = xf - fl;               // weight of j+1
    j0 = j < 0 ? 0 : j;
    j1 = (j + 1 > 31) ? 31 : (j + 1);
}

// ============================================================
// Kernel 2: 3x3 avg pool on p2 plane (32x32) then bilinear 32->64,
// write channels [512, 1536). One block per (b, c2).
// ============================================================
__global__ void pool2_resize_kernel(const float* __restrict__ p2) {
    __shared__ float s[HW2];
    __shared__ float q[HW2];
    int plane = blockIdx.x;                    // b*C2 + c
    const float* in = p2 + (size_t)plane * HW2;
    int b = plane / C2, c = plane - b * C2;
    float* out = g_sample + ((size_t)b * CTOT + C1 + c) * HW;
    for (int i = threadIdx.x; i < HW2; i += blockDim.x) s[i] = in[i];
    __syncthreads();
    for (int i = threadIdx.x; i < HW2; i += blockDim.x) {
        int y = i >> 5, x = i & 31;
        float sum = 0.f;
        #pragma unroll
        for (int dy = -1; dy <= 1; ++dy) {
            int yy = y + dy;
            if ((unsigned)yy < 32u) {
                const float* r = s + yy * 32;
                #pragma unroll
                for (int dx = -1; dx <= 1; ++dx) {
                    int xx = x + dx;
                    if ((unsigned)xx < 32u) sum += r[xx];
                }
            }
        }
        q[i] = sum * (1.f / 9.f);
    }
    __syncthreads();
    for (int i = threadIdx.x; i < HW; i += blockDim.x) {
        int y = i >> 6, x = i & 63;
        int y0, y1, x0, x1; float wy, wx;
        lin_taps(y, y0, y1, wy);
        lin_taps(x, x0, x1, wx);
        float v0 = q[y0 * 32 + x0] * (1.f - wx) + q[y0 * 32 + x1] * wx;
        float v1 = q[y1 * 32 + x0] * (1.f - wx) + q[y1 * 32 + x1] * wx;
        out[i] = v0 * (1.f - wy) + v1 * wy;
    }
}

// ============================================================
// Kernel 3: projection GEMM.
// emb[m, o] = sum_c sample[b(m)][c][hw(m)] * W[o][c] + bias[o]
// M = 65536, N = 256, K = 1536. Tiles 128x128, 8x8 micro-tile, K-step 8.
// A is M-contiguous (column-major), B is K-contiguous.
// ============================================================
__global__ void __launch_bounds__(256) proj_gemm_kernel(
    const float* __restrict__ W, const float* __restrict__ bias) {
    __shared__ float As[8][128];
    __shared__ float Bs[8][128];
    int t = threadIdx.x;
    int tx = t & 15, ty = t >> 4;
    int m0 = blockIdx.x * 128;
    int n0 = blockIdx.y * 128;
    int b = m0 >> 12;          // 128 | 4096 so whole tile is one batch
    int hw0 = m0 & 4095;

    int ak = t >> 5;           // 0..7   (k row in A tile)
    int am = (t & 31) << 2;    // 0..124 (m, float4)
    int bn = t >> 1;           // 0..127 (n row of W)
    int bk = (t & 1) << 2;     // 0 or 4 (k, float4)

    const float* Aptr = g_sample + ((size_t)b * CTOT + ak) * HW + hw0 + am;
    const float* Bptr = W + (size_t)(n0 + bn) * CTOT + bk;

    float acc[8][8];
    #pragma unroll
    for (int i = 0; i < 8; ++i)
        #pragma unroll
        for (int j = 0; j < 8; ++j) acc[i][j] = 0.f;

    for (int k0 = 0; k0 < CTOT; k0 += 8) {
        float4 av = *(const float4*)(Aptr + (size_t)k0 * HW);
        float4 bv = *(const float4*)(Bptr + k0);
        __syncthreads();
        *(float4*)&As[ak][am] = av;
        Bs[bk + 0][bn] = bv.x;
        Bs[bk + 1][bn] = bv.y;
        Bs[bk + 2][bn] = bv.z;
        Bs[bk + 3][bn] = bv.w;
        __syncthreads();
        #pragma unroll
        for (int kk = 0; kk < 8; ++kk) {
            float4 a0 = *(const float4*)&As[kk][ty * 8];
            float4 a1 = *(const float4*)&As[kk][ty * 8 + 4];
            float4 b0 = *(const float4*)&Bs[kk][tx * 8];
            float4 b1 = *(const float4*)&Bs[kk][tx * 8 + 4];
            float a[8] = {a0.x, a0.y, a0.z, a0.w, a1.x, a1.y, a1.z, a1.w};
            float bb[8] = {b0.x, b0.y, b0.z, b0.w, b1.x, b1.y, b1.z, b1.w};
            #pragma unroll
            for (int i = 0; i < 8; ++i)
                #pragma unroll
                for (int j = 0; j < 8; ++j)
                    acc[i][j] = fmaf(a[i], bb[j], acc[i][j]);
        }
    }

    float bs[8];
    #pragma unroll
    for (int j = 0; j < 8; ++j) bs[j] = bias[n0 + tx * 8 + j];

    #pragma unroll
    for (int i = 0; i < 8; ++i) {
        int m = m0 + ty * 8 + i;
        float* dst = g_emb + (size_t)m * OUTC + n0 + tx * 8;
        float4 o0, o1;
        o0.x = acc[i][0] + bs[0]; o0.y = acc[i][1] + bs[1];
        o0.z = acc[i][2] + bs[2]; o0.w = acc[i][3] + bs[3];
        o1.x = acc[i][4] + bs[4]; o1.y = acc[i][5] + bs[5];
        o1.z = acc[i][6] + bs[6]; o1.w = acc[i][7] + bs[7];
        *(float4*)dst = o0;
        *(float4*)(dst + 4) = o1;
    }
}

// ============================================================
// Kernel 4: squared norms. One warp per row:
// rows [0, NPIX) -> g_emb rows, rows [NPIX, NPIX+P) -> centroid rows.
// ============================================================
__global__ void norms_kernel(const float* __restrict__ cents) {
    int warp = (blockIdx.x * blockDim.x + threadIdx.x) >> 5;
    int lane = threadIdx.x & 31;
    const float* row;
    float* dst;
    if (warp < NPIX) {
        row = g_emb + (size_t)warp * OUTC;
        dst = g_en + warp;
    } else if (warp < NPIX + PP) {
        row = cents + (size_t)(warp - NPIX) * OUTC;
        dst = g_cn + (warp - NPIX);
    } else {
        return;
    }
    float s = 0.f;
    for (int k = lane; k < OUTC; k += 32) {
        float v = row[k];
        s = fmaf(v, v, s);
    }
    #pragma unroll
    for (int off = 16; off; off >>= 1) s += __shfl_xor_sync(0xffffffffu, s, off);
    if (lane == 0) *dst = s;
}

// ============================================================
// Kernel 5: distance GEMM + fused top-3 + softmin score.
// Block: 128 pixels x all 2048 centroids (16 chunks of 128).
// Thread owns 8 pixels x 8 centroid-cols per chunk and keeps a running
// per-pixel top-3 of (||c||^2 - 2 e.c) (||e||^2 added at the end; sqrt
// is monotone so selection on dist^2 is exact).
// ============================================================
__global__ void __launch_bounds__(256) dist_kernel(
    const float* __restrict__ cents, float* __restrict__ out) {
    __shared__ float smem[6144];               // 24 KB: A/B tiles, later top-3 merge
    float (*As)[128] = (float(*)[128])smem;            // [8][128]
    float (*Bs)[128] = (float(*)[128])(smem + 1024);   // [8][128]

    int t = threadIdx.x;
    int tx = t & 15, ty = t >> 4;
    int m0 = blockIdx.x * 128;
    int r = t >> 1;            // 0..127
    int kg = (t & 1) << 2;     // 0 or 4

    const float* Aptr = g_emb + (size_t)(m0 + r) * OUTC + kg;

    float top0[8], top1[8], top2[8];
    #pragma unroll
    for (int i = 0; i < 8; ++i) { top0[i] = 3.4e38f; top1[i] = 3.4e38f; top2[i] = 3.4e38f; }

    for (int ch = 0; ch < 16; ++ch) {
        int n0 = ch * 128;
        const float* Bptr = cents + (size_t)(n0 + r) * OUTC + kg;

        float acc[8][8];
        #pragma unroll
        for (int i = 0; i < 8; ++i)
            #pragma unroll
            for (int j = 0; j < 8; ++j) acc[i][j] = 0.f;

        for (int k0 = 0; k0 < OUTC; k0 += 8) {
            float4 av = *(const float4*)(Aptr + k0);
            float4 bv = *(const float4*)(Bptr + k0);
            __syncthreads();
            As[kg + 0][r] = av.x; As[kg + 1][r] = av.y;
            As[kg + 2][r] = av.z; As[kg + 3][r] = av.w;
            Bs[kg + 0][r] = bv.x; Bs[kg + 1][r] = bv.y;
            Bs[kg + 2][r] = bv.z; Bs[kg + 3][r] = bv.w;
            __syncthreads();
            #pragma unroll
            for (int kk = 0; kk < 8; ++kk) {
                float4 a0 = *(const float4*)&As[kk][ty * 8];
                float4 a1 = *(const float4*)&As[kk][ty * 8 + 4];
                float4 b0 = *(const float4*)&Bs[kk][tx * 8];
                float4 b1 = *(const float4*)&Bs[kk][tx * 8 + 4];
                float a[8] = {a0.x, a0.y, a0.z, a0.w, a1.x, a1.y, a1.z, a1.w};
                float bb[8] = {b0.x, b0.y, b0.z, b0.w, b1.x, b1.y, b1.z, b1.w};
                #pragma unroll
                for (int i = 0; i < 8; ++i)
                    #pragma unroll
                    for (int j = 0; j < 8; ++j)
                        acc[i][j] = fmaf(a[i], bb[j], acc[i][j]);
            }
        }

        #pragma unroll
        for (int j = 0; j < 8; ++j) {
            float cn = g_cn[n0 + tx * 8 + j];
            #pragma unroll
            for (int i = 0; i < 8; ++i) {
                float v = cn - 2.f * acc[i][j];
                if (v < top2[i]) {
                    if (v < top1[i]) {
                        top2[i] = top1[i];
                        if (v < top0[i]) { top1[i] = top0[i]; top0[i] = v; }
                        else             { top1[i] = v; }
                    } else {
                        top2[i] = v;
                    }
                }
            }
        }
    }

    __syncthreads();   // done with As/Bs; reuse smem for the merge
    #pragma unroll
    for (int i = 0; i < 8; ++i) {
        int pix = ty * 8 + i;
        float* dst = smem + pix * 48 + tx * 3;
        dst[0] = top0[i]; dst[1] = top1[i]; dst[2] = top2[i];
    }
    __syncthreads();

    if (t < 128) {
        float t0 = 3.4e38f, t1 = 3.4e38f, t2 = 3.4e38f;
        const float* src = smem + t * 48;
        #pragma unroll
        for (int q = 0; q < 48; ++q) {
            float v = src[q];
            if (v < t2) {
                if (v < t1) {
                    t2 = t1;
                    if (v < t0) { t1 = t0; t0 = v; }
                    else        { t1 = v; }
                } else {
                    t2 = v;
                }
            }
        }
        float en = g_en[m0 + t];
        float d0 = sqrtf(en + t0);
        float d1 = sqrtf(en + t1);
        float d2 = sqrtf(en + t2);
        float w0 = 1.f / (1.f + expf(d0 - d1) + expf(d0 - d2));
        out[m0 + t] = w0 * d0;
    }
}

// ============================================================
// Launcher
// ============================================================
extern "C" void kernel_launch(void* const* d_in, const int* in_sizes, int n_in,
                              void* d_out, int out_size) {
    const float* p1 = (const float*)d_in[0];
    const float* p2 = (const float*)d_in[1];
    const float* pw = (const float*)d_in[2];
    const float* pb = (const float*)d_in[3];
    const float* ce = (const float*)d_in[4];
    float* out = (float*)d_out;
    (void)in_sizes; (void)n_in; (void)out_size;   // K is fixed at 3

    pool1_kernel<<<BB * C1, 256>>>(p1);
    pool2_resize_kernel<<<BB * C2, 256>>>(p2);
    proj_gemm_kernel<<<dim3(512, 2), 256>>>(pw, pb);
    norms_kernel<<<(NPIX + PP) * 32 / 256, 256>>>(ce);
    dist_kernel<<<512, 256>>>(ce, out);
}

// round 4
// speedup vs baseline: 4.3157x; 4.2989x over previous
#include <cuda_runtime.h>
#include <cuda_fp16.h>
#include <cstdint>

#define BB 16
#define C1 512
#define C2 1024
#define CTOT 1536
#define HW 4096
#define HW2 1024
#define OUTC 256
#define PP 2048
#define NPIX 65536

// ---------------- device scratch ----------------
__device__ __align__(16) __half g_pool[(size_t)BB * CTOT * HW];   // [b][c][hw]
__device__ __align__(16) __half g_A1[(size_t)NPIX * CTOT];        // [pixel][c]
__device__ __align__(16) __half g_Wh[OUTC * CTOT];                // [o][c]
__device__ __align__(16) __half g_Ch[PP * OUTC];                  // [p][c]
__device__ __align__(16) __half g_embh[(size_t)NPIX * OUTC];      // [pixel][o]
__device__ float g_en[NPIX];
__device__ float g_cn[PP];

// ---------------- mma.sync helper ----------------
__device__ __forceinline__ void mma16816(float& c0, float& c1, float& c2, float& c3,
                                         uint32_t a0, uint32_t a1, uint32_t a2, uint32_t a3,
                                         uint32_t b0, uint32_t b1) {
    asm volatile(
        "mma.sync.aligned.m16n8k16.row.col.f32.f16.f16.f32 "
        "{%0,%1,%2,%3}, {%4,%5,%6,%7}, {%8,%9}, {%0,%1,%2,%3};"
        : "+f"(c0), "+f"(c1), "+f"(c2), "+f"(c3)
        : "r"(a0), "r"(a1), "r"(a2), "r"(a3), "r"(b0), "r"(b1));
}

// ============================================================
// Kernel 1: 3x3 avg pool on p1 -> g_pool channels [0,512), fp16
// ============================================================
__global__ void pool1_kernel(const float* __restrict__ p1) {
    __shared__ float s[HW];
    int plane = blockIdx.x;
    const float* in = p1 + (size_t)plane * HW;
    int b = plane / C1, c = plane - b * C1;
    __half* out = g_pool + ((size_t)b * CTOT + c) * HW;
    for (int i = threadIdx.x; i < HW; i += blockDim.x) s[i] = in[i];
    __syncthreads();
    for (int i = threadIdx.x; i < HW; i += blockDim.x) {
        int y = i >> 6, x = i & 63;
        float sum = 0.f;
        #pragma unroll
        for (int dy = -1; dy <= 1; ++dy) {
            int yy = y + dy;
            if ((unsigned)yy < 64u) {
                const float* r = s + yy * 64;
                #pragma unroll
                for (int dx = -1; dx <= 1; ++dx) {
                    int xx = x + dx;
                    if ((unsigned)xx < 64u) sum += r[xx];
                }
            }
        }
        out[i] = __float2half(sum * (1.f / 9.f));
    }
}

__device__ __forceinline__ void lin_taps(int i, int& j0, int& j1, float& w1) {
    float xf = 0.5f * (float)i - 0.25f;
    float fl = floorf(xf);
    int j = (int)fl;
    w1 = xf - fl;
    j0 = j < 0 ? 0 : j;
    j1 = (j + 1 > 31) ? 31 : (j + 1);
}

// ============================================================
// Kernel 2: pool(p2) + bilinear 32->64 -> g_pool channels [512,1536)
// ============================================================
__global__ void pool2_resize_kernel(const float* __restrict__ p2) {
    __shared__ float s[HW2];
    __shared__ float q[HW2];
    int plane = blockIdx.x;
    const float* in = p2 + (size_t)plane * HW2;
    int b = plane / C2, c = plane - b * C2;
    __half* out = g_pool + ((size_t)b * CTOT + C1 + c) * HW;
    for (int i = threadIdx.x; i < HW2; i += blockDim.x) s[i] = in[i];
    __syncthreads();
    for (int i = threadIdx.x; i < HW2; i += blockDim.x) {
        int y = i >> 5, x = i & 31;
        float sum = 0.f;
        #pragma unroll
        for (int dy = -1; dy <= 1; ++dy) {
            int yy = y + dy;
            if ((unsigned)yy < 32u) {
                const float* r = s + yy * 32;
                #pragma unroll
                for (int dx = -1; dx <= 1; ++dx) {
                    int xx = x + dx;
                    if ((unsigned)xx < 32u) sum += r[xx];
                }
            }
        }
        q[i] = sum * (1.f / 9.f);
    }
    __syncthreads();
    for (int i = threadIdx.x; i < HW; i += blockDim.x) {
        int y = i >> 6, x = i & 63;
        int y0, y1, x0, x1; float wy, wx;
        lin_taps(y, y0, y1, wy);
        lin_taps(x, x0, x1, wx);
        float v0 = q[y0 * 32 + x0] * (1.f - wx) + q[y0 * 32 + x1] * wx;
        float v1 = q[y1 * 32 + x0] * (1.f - wx) + q[y1 * 32 + x1] * wx;
        out[i] = __float2half(v0 * (1.f - wy) + v1 * wy);
    }
}

// ============================================================
// Kernel 3: transpose g_pool [b][c][hw] -> g_A1 [b*HW+hw][c]
// ============================================================
__global__ void __launch_bounds__(256) transpose_kernel() {
    __shared__ __half ts[64][66];
    int bid = blockIdx.x;
    int ht = bid & 63;
    int rest = bid >> 6;
    int ct = rest % (CTOT / 64);
    int b = rest / (CTOT / 64);
    const __half* in = g_pool + ((size_t)b * CTOT + ct * 64) * HW + ht * 64;
    int t = threadIdx.x, tx = t & 31, ty = t >> 5;
    #pragma unroll
    for (int it = 0; it < 8; ++it) {
        int cr = ty + it * 8;
        *(__half2*)&ts[cr][tx * 2] = *(const __half2*)(in + (size_t)cr * HW + tx * 2);
    }
    __syncthreads();
    #pragma unroll
    for (int it = 0; it < 8; ++it) {
        int pr = ty + it * 8;
        __half2 v = __halves2half2(ts[tx * 2][pr], ts[tx * 2 + 1][pr]);
        *(__half2*)(g_A1 + (size_t)(b * HW + ht * 64 + pr) * CTOT + ct * 64 + tx * 2) = v;
    }
}

// ============================================================
// Kernel 4a: W -> fp16     Kernel 4b: centroids -> fp16 + ||c||^2
// ============================================================
__global__ void convW_kernel(const float* __restrict__ w) {
    int i = blockIdx.x * 256 + threadIdx.x;
    if (i < OUTC * CTOT) g_Wh[i] = __float2half(w[i]);
}
__global__ void convC_kernel(const float* __restrict__ cents) {
    int warp = (blockIdx.x * blockDim.x + threadIdx.x) >> 5;
    int lane = threadIdx.x & 31;
    if (warp >= PP) return;
    float s = 0.f;
    for (int k = lane; k < OUTC; k += 32) {
        __half h = __float2half(cents[(size_t)warp * OUTC + k]);
        g_Ch[(size_t)warp * OUTC + k] = h;
        float f = __half2float(h);
        s = fmaf(f, f, s);
    }
    #pragma unroll
    for (int off = 16; off; off >>= 1) s += __shfl_xor_sync(0xffffffffu, s, off);
    if (lane == 0) g_cn[warp] = s;
}

// ============================================================
// Kernel 5: projection GEMM (HMMA).
// Block 64m x 256n, 8 warps (2m x 4n), warp tile 32x64, K-step 32,
// double-buffered smem. Epilogue: +bias, fp16 emb store, ||e||^2.
// smem layout (halves, dynamic):
//   As: 2 x [64][40]   @ 0       (10240 B)
//   Bs: 2 x [256][40]  @ 10240   (40960 B)
//   bias f32[256]      @ 51200   (1024 B)
//   en  f32[64]        @ 52224   (256 B)
// ============================================================
#define G1_LDA 40
#define G1_LDB 40
#define G1_ABUF (64 * G1_LDA * 2)
#define G1_BBUF (256 * G1_LDB * 2)
#define G1_BIAS_OFF (2 * G1_ABUF + 2 * G1_BBUF)
#define G1_EN_OFF   (G1_BIAS_OFF + 1024)
#define G1_SMEM     (G1_EN_OFF + 256)

__global__ void __launch_bounds__(256) gemm1_kernel(const float* __restrict__ bias) {
    extern __shared__ char smem[];
    __half* As = (__half*)smem;
    __half* Bs = (__half*)(smem + 2 * G1_ABUF);
    float* bias_s = (float*)(smem + G1_BIAS_OFF);
    float* en_s = (float*)(smem + G1_EN_OFF);

    const int t = threadIdx.x;
    const int w = t >> 5, lane = t & 31;
    const int warpm = w >> 2, warpn = w & 3;
    const int g = lane >> 2, tig = lane & 3;
    const int m0 = blockIdx.x * 64;

    bias_s[t] = bias[t];
    if (t < 64) en_s[t] = 0.f;

    // global load indices
    const int ar = t >> 2, aq = t & 3;                 // A: row 0..63, quad 0..3
    const int br = t >> 2, bq = t & 3;                 // B: 4 rows each

    float acc[2][8][4];
    #pragma unroll
    for (int mt = 0; mt < 2; ++mt)
        #pragma unroll
        for (int nt = 0; nt < 8; ++nt)
            #pragma unroll
            for (int q = 0; q < 4; ++q) acc[mt][nt][q] = 0.f;

    // preload tile 0
    {
        uint4 av = *(const uint4*)(g_A1 + (size_t)(m0 + ar) * CTOT + aq * 8);
        *(uint4*)(As + ar * G1_LDA + aq * 8) = av;
        #pragma unroll
        for (int i = 0; i < 4; ++i) {
            int r = br + 64 * i;
            uint4 bv = *(const uint4*)(g_Wh + (size_t)r * CTOT + bq * 8);
            *(uint4*)(Bs + r * G1_LDB + bq * 8) = bv;
        }
    }
    __syncthreads();

    const int NT = CTOT / 32;  // 48
    for (int kt = 0; kt < NT; ++kt) {
        int cur = kt & 1;
        uint4 av_n; uint4 bv_n[4];
        if (kt + 1 < NT) {
            int k0 = (kt + 1) * 32;
            av_n = *(const uint4*)(g_A1 + (size_t)(m0 + ar) * CTOT + k0 + aq * 8);
            #pragma unroll
            for (int i = 0; i < 4; ++i)
                bv_n[i] = *(const uint4*)(g_Wh + (size_t)(br + 64 * i) * CTOT + k0 + bq * 8);
        }

        const uint32_t* As32 = (const uint32_t*)(As + cur * (G1_ABUF / 2));
        const uint32_t* Bs32 = (const uint32_t*)(Bs + cur * (G1_BBUF / 2));
        #pragma unroll
        for (int ks = 0; ks < 2; ++ks) {
            int kq = ks * 8;
            uint32_t a[2][4];
            #pragma unroll
            for (int mt = 0; mt < 2; ++mt) {
                int row = warpm * 32 + mt * 16 + g;
                a[mt][0] = As32[row * (G1_LDA / 2) + kq + tig];
                a[mt][1] = As32[(row + 8) * (G1_LDA / 2) + kq + tig];
                a[mt][2] = As32[row * (G1_LDA / 2) + kq + tig + 4];
                a[mt][3] = As32[(row + 8) * (G1_LDA / 2) + kq + tig + 4];
            }
            #pragma unroll
            for (int nt = 0; nt < 8; ++nt) {
                int n = warpn * 64 + nt * 8 + g;
                uint32_t b0 = Bs32[n * (G1_LDB / 2) + kq + tig];
                uint32_t b1 = Bs32[n * (G1_LDB / 2) + kq + tig + 4];
                #pragma unroll
                for (int mt = 0; mt < 2; ++mt)
                    mma16816(acc[mt][nt][0], acc[mt][nt][1], acc[mt][nt][2], acc[mt][nt][3],
                             a[mt][0], a[mt][1], a[mt][2], a[mt][3], b0, b1);
            }
        }

        if (kt + 1 < NT) {
            int nxt = cur ^ 1;
            *(uint4*)(As + nxt * (G1_ABUF / 2) + ar * G1_LDA + aq * 8) = av_n;
            #pragma unroll
            for (int i = 0; i < 4; ++i)
                *(uint4*)(Bs + nxt * (G1_BBUF / 2) + (br + 64 * i) * G1_LDB + bq * 8) = bv_n[i];
        }
        __syncthreads();
    }

    // epilogue
    float en_loc[2][2] = {{0.f, 0.f}, {0.f, 0.f}};
    #pragma unroll
    for (int mt = 0; mt < 2; ++mt) {
        int row0 = warpm * 32 + mt * 16 + g;
        #pragma unroll
        for (int nt = 0; nt < 8; ++nt) {
            int col = warpn * 64 + nt * 8 + tig * 2;
            float f0 = acc[mt][nt][0] + bias_s[col];
            float f1 = acc[mt][nt][1] + bias_s[col + 1];
            __half2 h01 = __floats2half2_rn(f0, f1);
            *(uint32_t*)(g_embh + (size_t)(m0 + row0) * OUTC + col) = *(uint32_t*)&h01;
            float q0 = __half2float(__low2half(h01)), q1 = __half2float(__high2half(h01));
            en_loc[mt][0] = fmaf(q0, q0, fmaf(q1, q1, en_loc[mt][0]));

            float f2 = acc[mt][nt][2] + bias_s[col];
            float f3 = acc[mt][nt][3] + bias_s[col + 1];
            __half2 h23 = __floats2half2_rn(f2, f3);
            *(uint32_t*)(g_embh + (size_t)(m0 + row0 + 8) * OUTC + col) = *(uint32_t*)&h23;
            float q2 = __half2float(__low2half(h23)), q3 = __half2float(__high2half(h23));
            en_loc[mt][1] = fmaf(q2, q2, fmaf(q3, q3, en_loc[mt][1]));
        }
    }
    #pragma unroll
    for (int mt = 0; mt < 2; ++mt)
        #pragma unroll
        for (int hi = 0; hi < 2; ++hi) {
            float v = en_loc[mt][hi];
            v += __shfl_xor_sync(0xffffffffu, v, 1);
            v += __shfl_xor_sync(0xffffffffu, v, 2);
            if (tig == 0) atomicAdd(&en_s[warpm * 32 + mt * 16 + hi * 8 + g], v);
        }
    __syncthreads();
    if (t < 64) g_en[m0 + t] = en_s[t];
}

// ============================================================
// Kernel 6: distance GEMM (HMMA) + fused top-3 + softmin score.
// Block = 128 pixels. A resident [128][256] in smem. 16 chunks of 128
// centroids; each chunk: 4 double-buffered B slices [128][64].
// 8 warps (4m x 2n), warp tile 32x64.
// smem (halves, dynamic):
//   As [128][264]        @ 0        (67584 B)
//   Bs 2 x [128][72]     @ 67584    (36864 B)
//   cn f32[2048]         @ 104448   (8192 B)
//   merge (reuses Bs)
// ============================================================
#define G2_LDA 264
#define G2_LDB 72
#define G2_AS_BYTES (128 * G2_LDA * 2)
#define G2_BBUF (128 * G2_LDB * 2)
#define G2_CN_OFF (G2_AS_BYTES + 2 * G2_BBUF)
#define G2_SMEM (G2_CN_OFF + 8192)

__global__ void __launch_bounds__(256) gemm2_kernel(float* __restrict__ out) {
    extern __shared__ char smem[];
    __half* As = (__half*)smem;
    __half* Bs = (__half*)(smem + G2_AS_BYTES);
    float* cn_s = (float*)(smem + G2_CN_OFF);

    const int t = threadIdx.x;
    const int w = t >> 5, lane = t & 31;
    const int warpm = w >> 1, warpn = w & 1;
    const int g = lane >> 2, tig = lane & 3;
    const int m0 = blockIdx.x * 128;

    // load cn
    #pragma unroll
    for (int i = 0; i < 8; ++i) cn_s[t + 256 * i] = g_cn[t + 256 * i];

    // load resident A: [128][256] halves
    #pragma unroll
    for (int i = 0; i < 16; ++i) {
        int idx = t + 256 * i;
        int row = idx >> 5, q = idx & 31;
        uint4 v = *(const uint4*)(g_embh + (size_t)(m0 + row) * OUTC + q * 8);
        *(uint4*)(As + row * G2_LDA + q * 8) = v;
    }

    // B tile load indices
    const int brow = t >> 3, bq = t & 7;   // with idx = t + 256*i

    float t3[4][3];
    #pragma unroll
    for (int s = 0; s < 4; ++s) { t3[s][0] = 3.4e38f; t3[s][1] = 3.4e38f; t3[s][2] = 3.4e38f; }

    float acc[2][8][4];

    // preload B tile 0 (chunk 0, slice 0)
    #pragma unroll
    for (int i = 0; i < 4; ++i) {
        int idx = t + 256 * i;
        int row = idx >> 3, q = idx & 7;
        uint4 v = *(const uint4*)(g_Ch + (size_t)row * OUTC + q * 8);
        *(uint4*)(Bs + row * G2_LDB + q * 8) = v;
    }
    __syncthreads();

    for (int gi = 0; gi < 64; ++gi) {
        int cur = gi & 1;
        int chunk = gi >> 2, sl = gi & 3;

        uint4 nv[4];
        if (gi + 1 < 64) {
            int nchunk = (gi + 1) >> 2, nsl = (gi + 1) & 3;
            #pragma unroll
            for (int i = 0; i < 4; ++i) {
                int idx = t + 256 * i;
                int row = idx >> 3, q = idx & 7;
                nv[i] = *(const uint4*)(g_Ch + (size_t)(nchunk * 128 + row) * OUTC
                                        + nsl * 64 + q * 8);
            }
        }

        if (sl == 0) {
            #pragma unroll
            for (int mt = 0; mt < 2; ++mt)
                #pragma unroll
                for (int nt = 0; nt < 8; ++nt)
                    #pragma unroll
                    for (int q = 0; q < 4; ++q) acc[mt][nt][q] = 0.f;
        }

        const uint32_t* As32 = (const uint32_t*)As;
        const uint32_t* Bs32 = (const uint32_t*)(Bs + cur * (G2_BBUF / 2));
        #pragma unroll
        for (int ks = 0; ks < 4; ++ks) {
            int akq = (sl * 4 + ks) * 8;   // k16 offset in resident A (u32 units)
            int bkq = ks * 8;
            uint32_t a[2][4];
            #pragma unroll
            for (int mt = 0; mt < 2; ++mt) {
                int row = warpm * 32 + mt * 16 + g;
                a[mt][0] = As32[row * (G2_LDA / 2) + akq + tig];
                a[mt][1] = As32[(row + 8) * (G2_LDA / 2) + akq + tig];
                a[mt][2] = As32[row * (G2_LDA / 2) + akq + tig + 4];
                a[mt][3] = As32[(row + 8) * (G2_LDA / 2) + akq + tig + 4];
            }
            #pragma unroll
            for (int nt = 0; nt < 8; ++nt) {
                int n = warpn * 64 + nt * 8 + g;
                uint32_t b0 = Bs32[n * (G2_LDB / 2) + bkq + tig];
                uint32_t b1 = Bs32[n * (G2_LDB / 2) + bkq + tig + 4];
                #pragma unroll
                for (int mt = 0; mt < 2; ++mt)
                    mma16816(acc[mt][nt][0], acc[mt][nt][1], acc[mt][nt][2], acc[mt][nt][3],
                             a[mt][0], a[mt][1], a[mt][2], a[mt][3], b0, b1);
            }
        }

        if (sl == 3) {
            // epilogue for this chunk: v = cn - 2*dot; update top3
            #pragma unroll
            for (int mt = 0; mt < 2; ++mt) {
                #pragma unroll
                for (int nt = 0; nt < 8; ++nt) {
                    int col = chunk * 128 + warpn * 64 + nt * 8 + tig * 2;
                    float cn0 = cn_s[col], cn1 = cn_s[col + 1];
                    #pragma unroll
                    for (int hi = 0; hi < 2; ++hi) {
                        int s = mt * 2 + hi;
                        float v0 = cn0 - 2.f * acc[mt][nt][hi * 2 + 0];
                        float v1 = cn1 - 2.f * acc[mt][nt][hi * 2 + 1];
                        #pragma unroll
                        for (int e = 0; e < 2; ++e) {
                            float v = e ? v1 : v0;
                            if (v < t3[s][2]) {
                                if (v < t3[s][1]) {
                                    t3[s][2] = t3[s][1];
                                    if (v < t3[s][0]) { t3[s][1] = t3[s][0]; t3[s][0] = v; }
                                    else               { t3[s][1] = v; }
                                } else {
                                    t3[s][2] = v;
                                }
                            }
                        }
                    }
                }
            }
        }

        if (gi + 1 < 64) {
            __half* dstb = Bs + (cur ^ 1) * (G2_BBUF / 2);
            #pragma unroll
            for (int i = 0; i < 4; ++i) {
                int idx = t + 256 * i;
                int row = idx >> 3, q = idx & 7;
                *(uint4*)(dstb + row * G2_LDB + q * 8) = nv[i];
            }
        }
        __syncthreads();
    }

    // merge top3 across the 8 threads covering each pixel row
    float* mrg = (float*)(smem + G2_AS_BYTES);   // reuse B area: 128*8*3 floats
    #pragma unroll
    for (int mt = 0; mt < 2; ++mt)
        #pragma unroll
        for (int hi = 0; hi < 2; ++hi) {
            int row = warpm * 32 + mt * 16 + hi * 8 + g;
            int slot = warpn * 4 + tig;
            float* d = mrg + (row * 8 + slot) * 3;
            d[0] = t3[mt * 2 + hi][0];
            d[1] = t3[mt * 2 + hi][1];
            d[2] = t3[mt * 2 + hi][2];
        }
    __syncthreads();

    if (t < 128) {
        float b0 = 3.4e38f, b1 = 3.4e38f, b2 = 3.4e38f;
        const float* src = mrg + t * 24;
        #pragma unroll
        for (int q = 0; q < 24; ++q) {
            float v = src[q];
            if (v < b2) {
                if (v < b1) {
                    b2 = b1;
                    if (v < b0) { b1 = b0; b0 = v; }
                    else         { b1 = v; }
                } else {
                    b2 = v;
                }
            }
        }
        float en = g_en[m0 + t];
        float d0 = sqrtf(fmaxf(en + b0, 0.f));
        float d1 = sqrtf(fmaxf(en + b1, 0.f));
        float d2 = sqrtf(fmaxf(en + b2, 0.f));
        out[m0 + t] = d0 / (1.f + expf(d0 - d1) + expf(d0 - d2));
    }
}

// ============================================================
// Launcher
// ============================================================
extern "C" void kernel_launch(void* const* d_in, const int* in_sizes, int n_in,
                              void* d_out, int out_size) {
    const float* p1 = (const float*)d_in[0];
    const float* p2 = (const float*)d_in[1];
    const float* pw = (const float*)d_in[2];
    const float* pb = (const float*)d_in[3];
    const float* ce = (const float*)d_in[4];
    float* out = (float*)d_out;
    (void)in_sizes; (void)n_in; (void)out_size;

    cudaFuncSetAttribute(gemm1_kernel, cudaFuncAttributeMaxDynamicSharedMemorySize, G1_SMEM);
    cudaFuncSetAttribute(gemm2_kernel, cudaFuncAttributeMaxDynamicSharedMemorySize, G2_SMEM);

    pool1_kernel<<<BB * C1, 256>>>(p1);
    pool2_resize_kernel<<<BB * C2, 256>>>(p2);
    transpose_kernel<<<BB * (CTOT / 64) * (HW / 64), 256>>>();
    convW_kernel<<<(OUTC * CTOT + 255) / 256, 256>>>(pw);
    convC_kernel<<<PP / 8, 256>>>(ce);
    gemm1_kernel<<<NPIX / 64, 256, G1_SMEM>>>(pb);
    gemm2_kernel<<<NPIX / 128, 256, G2_SMEM>>>(out);
}

// round 5
// speedup vs baseline: 4.9804x; 1.1540x over previous
#include <cuda_runtime.h>
#include <cuda_fp16.h>
#include <cstdint>

#define BB 16
#define C1 512
#define C2 1024
#define CTOT 1536
#define HW 4096
#define HW2 1024
#define OUTC 256
#define PP 2048
#define NPIX 65536

// ---------------- device scratch ----------------
__device__ __align__(16) __half g_pool[(size_t)BB * CTOT * HW];   // [b][c][hw]
__device__ __align__(16) __half g_Wh[OUTC * CTOT];                // [o][c]
__device__ __align__(16) __half g_Ch[PP * OUTC];                  // [p][c]
__device__ __align__(16) __half g_embh[(size_t)NPIX * OUTC];      // [pixel][o]
__device__ float g_en[NPIX];
__device__ float g_cn[PP];

// ---------------- asm helpers ----------------
__device__ __forceinline__ uint32_t smem_u32(const void* p) {
    uint32_t a;
    asm("{ .reg .u64 t; cvta.to.shared.u64 t, %1; cvt.u32.u64 %0, t; }" : "=r"(a) : "l"(p));
    return a;
}
__device__ __forceinline__ void mma16816(float& c0, float& c1, float& c2, float& c3,
                                         uint32_t a0, uint32_t a1, uint32_t a2, uint32_t a3,
                                         uint32_t b0, uint32_t b1) {
    asm volatile(
        "mma.sync.aligned.m16n8k16.row.col.f32.f16.f16.f32 "
        "{%0,%1,%2,%3}, {%4,%5,%6,%7}, {%8,%9}, {%0,%1,%2,%3};"
        : "+f"(c0), "+f"(c1), "+f"(c2), "+f"(c3)
        : "r"(a0), "r"(a1), "r"(a2), "r"(a3), "r"(b0), "r"(b1));
}
__device__ __forceinline__ void ldsm4(uint32_t* d, uint32_t addr) {
    asm volatile("ldmatrix.sync.aligned.m8n8.x4.shared.b16 {%0,%1,%2,%3}, [%4];"
                 : "=r"(d[0]), "=r"(d[1]), "=r"(d[2]), "=r"(d[3]) : "r"(addr));
}
__device__ __forceinline__ void ldsm4t(uint32_t* d, uint32_t addr) {
    asm volatile("ldmatrix.sync.aligned.m8n8.x4.trans.shared.b16 {%0,%1,%2,%3}, [%4];"
                 : "=r"(d[0]), "=r"(d[1]), "=r"(d[2]), "=r"(d[3]) : "r"(addr));
}
__device__ __forceinline__ void cp16(uint32_t dst, const void* src) {
    asm volatile("cp.async.cg.shared.global [%0], [%1], 16;" :: "r"(dst), "l"(src));
}
#define CP_COMMIT() asm volatile("cp.async.commit_group;" ::: "memory")
#define CP_WAIT0()  asm volatile("cp.async.wait_group 0;" ::: "memory")

// ============================================================
// Kernel 1: 3x3 avg pool on p1 -> g_pool channels [0,512), fp16
// ============================================================
__global__ void pool1_kernel(const float* __restrict__ p1) {
    __shared__ float s[HW];
    int plane = blockIdx.x;
    const float* in = p1 + (size_t)plane * HW;
    int b = plane / C1, c = plane - b * C1;
    __half* out = g_pool + ((size_t)b * CTOT + c) * HW;
    for (int i = threadIdx.x; i < HW; i += blockDim.x) s[i] = in[i];
    __syncthreads();
    for (int i = threadIdx.x; i < HW; i += blockDim.x) {
        int y = i >> 6, x = i & 63;
        float sum = 0.f;
        #pragma unroll
        for (int dy = -1; dy <= 1; ++dy) {
            int yy = y + dy;
            if ((unsigned)yy < 64u) {
                const float* r = s + yy * 64;
                #pragma unroll
                for (int dx = -1; dx <= 1; ++dx) {
                    int xx = x + dx;
                    if ((unsigned)xx < 64u) sum += r[xx];
                }
            }
        }
        out[i] = __float2half(sum * (1.f / 9.f));
    }
}

__device__ __forceinline__ void lin_taps(int i, int& j0, int& j1, float& w1) {
    float xf = 0.5f * (float)i - 0.25f;
    float fl = floorf(xf);
    int j = (int)fl;
    w1 = xf - fl;
    j0 = j < 0 ? 0 : j;
    j1 = (j + 1 > 31) ? 31 : (j + 1);
}

// ============================================================
// Kernel 2: pool(p2) + bilinear 32->64 -> g_pool channels [512,1536)
// ============================================================
__global__ void pool2_resize_kernel(const float* __restrict__ p2) {
    __shared__ float s[HW2];
    __shared__ float q[HW2];
    int plane = blockIdx.x;
    const float* in = p2 + (size_t)plane * HW2;
    int b = plane / C2, c = plane - b * C2;
    __half* out = g_pool + ((size_t)b * CTOT + C1 + c) * HW;
    for (int i = threadIdx.x; i < HW2; i += blockDim.x) s[i] = in[i];
    __syncthreads();
    for (int i = threadIdx.x; i < HW2; i += blockDim.x) {
        int y = i >> 5, x = i & 31;
        float sum = 0.f;
        #pragma unroll
        for (int dy = -1; dy <= 1; ++dy) {
            int yy = y + dy;
            if ((unsigned)yy < 32u) {
                const float* r = s + yy * 32;
                #pragma unroll
                for (int dx = -1; dx <= 1; ++dx) {
                    int xx = x + dx;
                    if ((unsigned)xx < 32u) sum += r[xx];
                }
            }
        }
        q[i] = sum * (1.f / 9.f);
    }
    __syncthreads();
    for (int i = threadIdx.x; i < HW; i += blockDim.x) {
        int y = i >> 6, x = i & 63;
        int y0, y1, x0, x1; float wy, wx;
        lin_taps(y, y0, y1, wy);
        lin_taps(x, x0, x1, wx);
        float v0 = q[y0 * 32 + x0] * (1.f - wx) + q[y0 * 32 + x1] * wx;
        float v1 = q[y1 * 32 + x0] * (1.f - wx) + q[y1 * 32 + x1] * wx;
        out[i] = __float2half(v0 * (1.f - wy) + v1 * wy);
    }
}

// ============================================================
// Kernel 3a: W -> fp16     Kernel 3b: centroids -> fp16 + ||c||^2
// ============================================================
__global__ void convW_kernel(const float* __restrict__ w) {
    int i = blockIdx.x * 256 + threadIdx.x;
    if (i < OUTC * CTOT) g_Wh[i] = __float2half(w[i]);
}
__global__ void convC_kernel(const float* __restrict__ cents) {
    int warp = (blockIdx.x * blockDim.x + threadIdx.x) >> 5;
    int lane = threadIdx.x & 31;
    if (warp >= PP) return;
    float s = 0.f;
    for (int k = lane; k < OUTC; k += 32) {
        __half h = __float2half(cents[(size_t)warp * OUTC + k]);
        g_Ch[(size_t)warp * OUTC + k] = h;
        float f = __half2float(h);
        s = fmaf(f, f, s);
    }
    #pragma unroll
    for (int off = 16; off; off >>= 1) s += __shfl_xor_sync(0xffffffffu, s, off);
    if (lane == 0) g_cn[warp] = s;
}

// ============================================================
// Kernel 4: projection GEMM (HMMA, ldmatrix, cp.async).
// Block 128m x 256n, 8 warps (2m x 4n), warp 64x64, K-step 32.
// A read K-major straight from g_pool ([c][hw]); trans-ldmatrix.
// smem (bytes):
//   As 2 x [32][136]h  @ 0      (17408)
//   Bs 2 x [256][40]h  @ 17408  (40960)
//   bias f32[256]      @ 58368
//   en   f32[128]      @ 59392
// ============================================================
#define G1_LDA 136
#define G1_ABUF 8704
#define G1_LDB 40
#define G1_BBUF 20480
#define G1_BS_OFF 17408
#define G1_BIAS_OFF 58368
#define G1_EN_OFF 59392
#define G1_SMEM (G1_EN_OFF + 512)

__global__ void __launch_bounds__(256) gemm1_kernel(const float* __restrict__ bias) {
    extern __shared__ char smem[];
    const uint32_t sb = smem_u32(smem);
    float* bias_s = (float*)(smem + G1_BIAS_OFF);
    float* en_s = (float*)(smem + G1_EN_OFF);

    const int t = threadIdx.x;
    const int w = t >> 5, lane = t & 31;
    const int warpm = w >> 2, warpn = w & 3;
    const int g = lane >> 2, tig = lane & 3;
    const int j = lane >> 3, r = lane & 7;
    const int m0 = blockIdx.x * 128;
    const int b = m0 >> 12, hw0 = m0 & 4095;

    bias_s[t] = bias[t];
    if (t < 128) en_s[t] = 0.f;

    // tile-load indices
    const int ak = t >> 4, am8 = (t & 15) * 8;          // A: 2 rows-of-16 per thread pass
    const int bn = t >> 2, bkq = (t & 3) * 8;           // B: 4 passes
    const __half* apsrc = g_pool + ((size_t)b * CTOT + ak) * HW + hw0 + am8;
    const __half* bpsrc = g_Wh + (size_t)bn * CTOT + bkq;
    const uint32_t adst = sb + (ak * G1_LDA + am8) * 2;
    const uint32_t bdst = sb + G1_BS_OFF + (bn * G1_LDB + bkq) * 2;

    // fragment base addresses (per lane)
    const uint32_t abase = sb + (((j >> 1) * 8 + r) * G1_LDA + warpm * 64 + (j & 1) * 8) * 2;
    const uint32_t bbase = sb + G1_BS_OFF +
                           ((warpn * 64 + (j & 1) * 8 + r) * G1_LDB + (j >> 1) * 8) * 2;

    float acc[4][8][4];
    #pragma unroll
    for (int mt = 0; mt < 4; ++mt)
        #pragma unroll
        for (int nt = 0; nt < 8; ++nt)
            #pragma unroll
            for (int q = 0; q < 4; ++q) acc[mt][nt][q] = 0.f;

    // prologue: tile 0
    #pragma unroll
    for (int i = 0; i < 2; ++i)
        cp16(adst + i * 16 * G1_LDA * 2, apsrc + (size_t)(16 * i) * HW);
    #pragma unroll
    for (int i = 0; i < 4; ++i)
        cp16(bdst + i * 64 * G1_LDB * 2, bpsrc + (size_t)(64 * i) * CTOT);
    CP_COMMIT();

    const int NT = CTOT / 32;  // 48
    for (int kt = 0; kt < NT; ++kt) {
        CP_WAIT0();
        __syncthreads();
        if (kt + 1 < NT) {
            int k0 = (kt + 1) * 32;
            uint32_t ao = ((kt + 1) & 1) * G1_ABUF;
            uint32_t bo = ((kt + 1) & 1) * G1_BBUF;
            #pragma unroll
            for (int i = 0; i < 2; ++i)
                cp16(adst + ao + i * 16 * G1_LDA * 2, apsrc + (size_t)(k0 + 16 * i) * HW);
            #pragma unroll
            for (int i = 0; i < 4; ++i)
                cp16(bdst + bo + i * 64 * G1_LDB * 2, bpsrc + (size_t)(64 * i) * CTOT + k0);
            CP_COMMIT();
        }
        uint32_t aab = abase + (kt & 1) * G1_ABUF;
        uint32_t bbb = bbase + (kt & 1) * G1_BBUF;
        #pragma unroll
        for (int ks = 0; ks < 2; ++ks) {
            int ks16 = ks * 16;
            uint32_t a[4][4], bf[4][4];
            #pragma unroll
            for (int mt = 0; mt < 4; ++mt)
                ldsm4t(a[mt], aab + (ks16 * G1_LDA + mt * 16) * 2);
            #pragma unroll
            for (int ng = 0; ng < 4; ++ng)
                ldsm4(bf[ng], bbb + (ng * 16 * G1_LDB + ks16) * 2);
            #pragma unroll
            for (int mt = 0; mt < 4; ++mt)
                #pragma unroll
                for (int ng = 0; ng < 4; ++ng) {
                    mma16816(acc[mt][2*ng][0], acc[mt][2*ng][1], acc[mt][2*ng][2], acc[mt][2*ng][3],
                             a[mt][0], a[mt][1], a[mt][2], a[mt][3], bf[ng][0], bf[ng][2]);
                    mma16816(acc[mt][2*ng+1][0], acc[mt][2*ng+1][1], acc[mt][2*ng+1][2], acc[mt][2*ng+1][3],
                             a[mt][0], a[mt][1], a[mt][2], a[mt][3], bf[ng][1], bf[ng][3]);
                }
        }
    }
    __syncthreads();

    // epilogue: +bias, fp16 emb store, ||e||^2 partials
    #pragma unroll
    for (int mt = 0; mt < 4; ++mt) {
        int row0 = warpm * 64 + mt * 16 + g;
        float en0 = 0.f, en1 = 0.f;
        #pragma unroll
        for (int nt = 0; nt < 8; ++nt) {
            int col = warpn * 64 + nt * 8 + tig * 2;
            float f0 = acc[mt][nt][0] + bias_s[col];
            float f1 = acc[mt][nt][1] + bias_s[col + 1];
            __half2 h01 = __floats2half2_rn(f0, f1);
            *(uint32_t*)(g_embh + (size_t)(m0 + row0) * OUTC + col) = *(uint32_t*)&h01;
            float q0 = __half2float(__low2half(h01)), q1 = __half2float(__high2half(h01));
            en0 = fmaf(q0, q0, fmaf(q1, q1, en0));

            float f2 = acc[mt][nt][2] + bias_s[col];
            float f3 = acc[mt][nt][3] + bias_s[col + 1];
            __half2 h23 = __floats2half2_rn(f2, f3);
            *(uint32_t*)(g_embh + (size_t)(m0 + row0 + 8) * OUTC + col) = *(uint32_t*)&h23;
            float q2 = __half2float(__low2half(h23)), q3 = __half2float(__high2half(h23));
            en1 = fmaf(q2, q2, fmaf(q3, q3, en1));
        }
        en0 += __shfl_xor_sync(0xffffffffu, en0, 1);
        en0 += __shfl_xor_sync(0xffffffffu, en0, 2);
        en1 += __shfl_xor_sync(0xffffffffu, en1, 1);
        en1 += __shfl_xor_sync(0xffffffffu, en1, 2);
        if (tig == 0) {
            atomicAdd(&en_s[warpm * 64 + mt * 16 + g], en0);
            atomicAdd(&en_s[warpm * 64 + mt * 16 + 8 + g], en1);
        }
    }
    __syncthreads();
    if (t < 128) g_en[m0 + t] = en_s[t];
}

// ============================================================
// Kernel 5: distance GEMM (HMMA, ldmatrix, cp.async) + top-3 + score.
// Block 128 pixels x 2048 centroids (16 chunks x 4 slices of k64).
// 8 warps (4m x 2n), warp 32x64. A resident.
// smem:
//   As [128][264]h   @ 0       (67584)
//   Bs 2 x [128][72]h @ 67584  (36864)
//   cn f32[2048]     @ 104448  (8192)
// ============================================================
#define G2_LDA 264
#define G2_LDB 72
#define G2_AS_BYTES 67584
#define G2_BBUF 18432
#define G2_CN_OFF (G2_AS_BYTES + 2 * G2_BBUF)
#define G2_SMEM (G2_CN_OFF + 8192)

__global__ void __launch_bounds__(256) gemm2_kernel(float* __restrict__ out) {
    extern __shared__ char smem[];
    const uint32_t sb = smem_u32(smem);
    __half* As = (__half*)smem;
    float* cn_s = (float*)(smem + G2_CN_OFF);

    const int t = threadIdx.x;
    const int w = t >> 5, lane = t & 31;
    const int warpm = w >> 1, warpn = w & 1;
    const int g = lane >> 2, tig = lane & 3;
    const int j = lane >> 3, r = lane & 7;
    const int m0 = blockIdx.x * 128;

    #pragma unroll
    for (int i = 0; i < 8; ++i) cn_s[t + 256 * i] = g_cn[t + 256 * i];

    // resident A [128][256]
    #pragma unroll
    for (int i = 0; i < 16; ++i) {
        int idx = t + 256 * i;
        int row = idx >> 5, q = idx & 31;
        uint4 v = *(const uint4*)(g_embh + (size_t)(m0 + row) * OUTC + q * 8);
        *(uint4*)(As + row * G2_LDA + q * 8) = v;
    }

    // B tile load indices (4 x 16B per thread per slice)
    const int brow = t >> 3, bq = (t & 7) * 8;
    const uint32_t bdst = sb + G2_AS_BYTES + (brow * G2_LDB + bq) * 2;

    // fragment bases
    const uint32_t abase = sb + ((warpm * 32 + (j & 1) * 8 + r) * G2_LDA + (j >> 1) * 8) * 2;
    const uint32_t bbase = sb + G2_AS_BYTES +
                           ((warpn * 64 + (j & 1) * 8 + r) * G2_LDB + (j >> 1) * 8) * 2;

    float t3[4][3];
    #pragma unroll
    for (int s = 0; s < 4; ++s) { t3[s][0] = 3.4e38f; t3[s][1] = 3.4e38f; t3[s][2] = 3.4e38f; }

    float acc[2][8][4];

    // prologue: slice 0
    #pragma unroll
    for (int i = 0; i < 4; ++i)
        cp16(bdst + i * 32 * G2_LDB * 2, g_Ch + (size_t)(brow + 32 * i) * OUTC + bq);
    CP_COMMIT();
    __syncthreads();   // A resident ready too

    for (int gi = 0; gi < 64; ++gi) {
        int cur = gi & 1;
        int chunk = gi >> 2, sl = gi & 3;

        CP_WAIT0();
        __syncthreads();
        if (gi + 1 < 64) {
            int nchunk = (gi + 1) >> 2, nsl = (gi + 1) & 3;
            uint32_t bo = ((gi + 1) & 1) * G2_BBUF;
            const __half* src = g_Ch + (size_t)(nchunk * 128 + brow) * OUTC + nsl * 64 + bq;
            #pragma unroll
            for (int i = 0; i < 4; ++i)
                cp16(bdst + bo + i * 32 * G2_LDB * 2, src + (size_t)(32 * i) * OUTC);
            CP_COMMIT();
        }

        if (sl == 0) {
            #pragma unroll
            for (int mt = 0; mt < 2; ++mt)
                #pragma unroll
                for (int nt = 0; nt < 8; ++nt)
                    #pragma unroll
                    for (int q = 0; q < 4; ++q) acc[mt][nt][q] = 0.f;
        }

        uint32_t bbb = bbase + cur * G2_BBUF;
        #pragma unroll
        for (int ks = 0; ks < 4; ++ks) {
            int ks16 = ks * 16;
            int kk = sl * 64 + ks16;
            uint32_t a[2][4], bf[4][4];
            #pragma unroll
            for (int mt = 0; mt < 2; ++mt)
                ldsm4(a[mt], abase + (mt * 16 * G2_LDA + kk) * 2);
            #pragma unroll
            for (int ng = 0; ng < 4; ++ng)
                ldsm4(bf[ng], bbb + (ng * 16 * G2_LDB + ks16) * 2);
            #pragma unroll
            for (int mt = 0; mt < 2; ++mt)
                #pragma unroll
                for (int ng = 0; ng < 4; ++ng) {
                    mma16816(acc[mt][2*ng][0], acc[mt][2*ng][1], acc[mt][2*ng][2], acc[mt][2*ng][3],
                             a[mt][0], a[mt][1], a[mt][2], a[mt][3], bf[ng][0], bf[ng][2]);
                    mma16816(acc[mt][2*ng+1][0], acc[mt][2*ng+1][1], acc[mt][2*ng+1][2], acc[mt][2*ng+1][3],
                             a[mt][0], a[mt][1], a[mt][2], a[mt][3], bf[ng][1], bf[ng][3]);
                }
        }

        if (sl == 3) {
            #pragma unroll
            for (int mt = 0; mt < 2; ++mt) {
                #pragma unroll
                for (int nt = 0; nt < 8; ++nt) {
                    int col = chunk * 128 + warpn * 64 + nt * 8 + tig * 2;
                    float cn0 = cn_s[col], cn1 = cn_s[col + 1];
                    #pragma unroll
                    for (int hi = 0; hi < 2; ++hi) {
                        int s = mt * 2 + hi;
                        float v0 = cn0 - 2.f * acc[mt][nt][hi * 2 + 0];
                        float v1 = cn1 - 2.f * acc[mt][nt][hi * 2 + 1];
                        #pragma unroll
                        for (int e = 0; e < 2; ++e) {
                            float v = e ? v1 : v0;
                            if (v < t3[s][2]) {
                                if (v < t3[s][1]) {
                                    t3[s][2] = t3[s][1];
                                    if (v < t3[s][0]) { t3[s][1] = t3[s][0]; t3[s][0] = v; }
                                    else               { t3[s][1] = v; }
                                } else {
                                    t3[s][2] = v;
                                }
                            }
                        }
                    }
                }
            }
        }
    }
    __syncthreads();

    // merge top3 across 8 (warpn, tig) slots per pixel row
    float* mrg = (float*)(smem + G2_AS_BYTES);
    #pragma unroll
    for (int mt = 0; mt < 2; ++mt)
        #pragma unroll
        for (int hi = 0; hi < 2; ++hi) {
            int row = warpm * 32 + mt * 16 + hi * 8 + g;
            int slot = warpn * 4 + tig;
            float* d = mrg + (row * 8 + slot) * 3;
            d[0] = t3[mt * 2 + hi][0];
            d[1] = t3[mt * 2 + hi][1];
            d[2] = t3[mt * 2 + hi][2];
        }
    __syncthreads();

    if (t < 128) {
        float b0 = 3.4e38f, b1 = 3.4e38f, b2 = 3.4e38f;
        const float* src = mrg + t * 24;
        #pragma unroll
        for (int q = 0; q < 24; ++q) {
            float v = src[q];
            if (v < b2) {
                if (v < b1) {
                    b2 = b1;
                    if (v < b0) { b1 = b0; b0 = v; }
                    else         { b1 = v; }
                } else {
                    b2 = v;
                }
            }
        }
        float en = g_en[m0 + t];
        float d0 = sqrtf(fmaxf(en + b0, 0.f));
        float d1 = sqrtf(fmaxf(en + b1, 0.f));
        float d2 = sqrtf(fmaxf(en + b2, 0.f));
        out[m0 + t] = d0 / (1.f + expf(d0 - d1) + expf(d0 - d2));
    }
}

// ============================================================
// Launcher
// ============================================================
extern "C" void kernel_launch(void* const* d_in, const int* in_sizes, int n_in,
                              void* d_out, int out_size) {
    const float* p1 = (const float*)d_in[0];
    const float* p2 = (const float*)d_in[1];
    const float* pw = (const float*)d_in[2];
    const float* pb = (const float*)d_in[3];
    const float* ce = (const float*)d_in[4];
    float* out = (float*)d_out;
    (void)in_sizes; (void)n_in; (void)out_size;

    cudaFuncSetAttribute(gemm1_kernel, cudaFuncAttributeMaxDynamicSharedMemorySize, G1_SMEM);
    cudaFuncSetAttribute(gemm2_kernel, cudaFuncAttributeMaxDynamicSharedMemorySize, G2_SMEM);

    pool1_kernel<<<BB * C1, 256>>>(p1);
    pool2_resize_kernel<<<BB * C2, 256>>>(p2);
    convW_kernel<<<(OUTC * CTOT + 255) / 256, 256>>>(pw);
    convC_kernel<<<PP / 8, 256>>>(ce);
    gemm1_kernel<<<NPIX / 128, 256, G1_SMEM>>>(pb);
    gemm2_kernel<<<NPIX / 128, 256, G2_SMEM>>>(out);
}